// round 12
// baseline (speedup 1.0000x reference)
#include <cuda_runtime.h>
#include <math.h>

#define BB 4
#define TT 2048
#define EE 1024
#define HH 64
#define MM (BB*TT)

// device scratch (module statics: allocation-free)
__device__ float g_q[MM*HH];
__device__ float g_k[MM*HH];
__device__ float g_v[MM*HH];
// split-KV partials: pidx = (b*32 + qtile)*4 + chunk
__device__ float g_po[512*64*64];
__device__ float g_ml[512*64*2];

__device__ __forceinline__ unsigned f2tf32(float f) {
    unsigned u;
    asm("cvt.rna.tf32.f32 %0, %1;" : "=r"(u) : "f"(f));
    return u;
}
__device__ __forceinline__ unsigned u2tf32(unsigned ub) {
    unsigned u;
    asm("cvt.rna.tf32.f32 %0, %1;" : "=r"(u) : "f"(__uint_as_float(ub)));
    return u;
}
__device__ __forceinline__ float ex2(float x) {
    float y;
    asm("ex2.approx.ftz.f32 %0, %1;" : "=f"(y) : "f"(x));
    return y;
}
__device__ __forceinline__ void mma_tf32(float c[4], unsigned a0, unsigned a1,
                                         unsigned a2, unsigned a3,
                                         unsigned b0, unsigned b1) {
    asm volatile(
        "mma.sync.aligned.m16n8k8.row.col.f32.tf32.tf32.f32 "
        "{%0,%1,%2,%3}, {%4,%5,%6,%7}, {%8,%9}, {%0,%1,%2,%3};"
        : "+f"(c[0]), "+f"(c[1]), "+f"(c[2]), "+f"(c[3])
        : "r"(a0), "r"(a1), "r"(a2), "r"(a3), "r"(b0), "r"(b1));
}
#define LDSM4(r0,r1,r2,r3,addr) \
    asm volatile("ldmatrix.sync.aligned.m8n8.x4.shared.b16 {%0,%1,%2,%3}, [%4];" \
                 : "=r"(r0), "=r"(r1), "=r"(r2), "=r"(r3) : "r"(addr))

__device__ __forceinline__ void cp16(void* smem, const void* gmem) {
    unsigned sa = (unsigned)__cvta_generic_to_shared(smem);
    asm volatile("cp.async.cg.shared.global [%0], [%1], 16;" :: "r"(sa), "l"(gmem));
}
#define CP_COMMIT() asm volatile("cp.async.commit_group;")
#define CP_WAIT0()  asm volatile("cp.async.wait_group 0;")
#define CP_WAIT1()  asm volatile("cp.async.wait_group 1;")

__device__ __forceinline__ void mbar_init(unsigned addr, unsigned cnt) {
    asm volatile("mbarrier.init.shared.b64 [%0], %1;" :: "r"(addr), "r"(cnt) : "memory");
}
__device__ __forceinline__ void mbar_expect_tx(unsigned addr, unsigned bytes) {
    asm volatile("mbarrier.arrive.expect_tx.shared.b64 _, [%0], %1;"
                 :: "r"(addr), "r"(bytes) : "memory");
}
__device__ __forceinline__ void mbar_wait(unsigned addr, unsigned parity) {
    asm volatile(
        "{\n\t.reg .pred P1;\n\t"
        "W_%=:\n\t"
        "mbarrier.try_wait.parity.acquire.cta.shared::cta.b64 P1, [%0], %1, 0x989680;\n\t"
        "@P1 bra.uni D_%=;\n\t"
        "bra.uni W_%=;\n\t"
        "D_%=:\n\t}"
        :: "r"(addr), "r"(parity) : "memory");
}
__device__ __forceinline__ void cp_bulk(unsigned dst, const void* src,
                                        unsigned bytes, unsigned mbar) {
    asm volatile(
        "cp.async.bulk.shared::cluster.global.mbarrier::complete_tx::bytes "
        "[%0], [%1], %2, [%3];"
        :: "r"(dst), "l"(src), "r"(bytes), "r"(mbar) : "memory");
}

// ---------------------------------------------------------------------------
// Kernel 1: FUSED QKV projection, tf32 mma.sync + ldmatrix + cp.async.bulk.
// grid 128 (64 rows/block), block 256 (8 warps).
// Warp tiling 2m x 2n x 2k: m0=(w&1)*32, n0=((w>>1)&1)*32, kg=w>>2 handles
// k-half (32 floats) of each 64-wide K-chunk.  16 chunks, 3-stage ring.
// Loads: cp.async.bulk, ONE 256B op per row per slab (256 ops/chunk total,
// issued by warp 0) -> LDGSTS issue-rate bottleneck eliminated.
// expect_tx = ACTUAL transfer bytes 256*256 = 65536 (NOT the padded stage
// footprint — R11 armed 69632 and deadlocked).
// Stage: 4 slabs x 64 rows x pitch 68 floats = 69632 B; 3 stages = 208896 B.
// Pitch 68 (= 17 x 16B): 8 consecutive rows hit distinct 16B lanes -> LDSM ok.
// kg=1 partials reduced into kg=0 via smem at the end.
// ---------------------------------------------------------------------------
#define PJ_PITCH 68
#define PJ_SLABF (64*PJ_PITCH)           // 4352 floats
#define PJ_STAGEF (4*PJ_SLABF)           // 17408 floats
#define PJ_STAGEB (PJ_STAGEF*4)          // 69632 bytes (padded footprint)
#define PJ_XFERB  65536u                 // bytes actually transferred per stage
#define PJ_SM_BYTES (3*PJ_STAGEB + 64)   // 208960

__global__ __launch_bounds__(256) void proj_kernel(
    const float* __restrict__ x,
    const float* __restrict__ Wq, const float* __restrict__ bq,
    const float* __restrict__ Wk, const float* __restrict__ bk,
    const float* __restrict__ Wv, const float* __restrict__ bv)
{
    extern __shared__ __align__(16) float psm[];

    const int row0 = blockIdx.x * 64;
    const int tid  = threadIdx.x;
    const int wid  = tid >> 5, l = tid & 31;
    const int g    = l >> 2, tg = l & 3;
    const int m0   = (wid & 1) * 32;
    const int n0   = ((wid >> 1) & 1) * 32;
    const int kg   = wid >> 2;

    const unsigned smb = (unsigned)__cvta_generic_to_shared(psm);
    const unsigned mb0 = smb + 3 * PJ_STAGEB;     // 3 mbarriers, 8B each

    if (tid == 0) { mbar_init(mb0, 1); mbar_init(mb0 + 8, 1); mbar_init(mb0 + 16, 1); }
    __syncthreads();
    asm volatile("fence.proxy.async.shared::cta;" ::: "memory");

    const float* slab0 = x + (size_t)row0 * EE;
    const float* slabs[4] = {slab0, Wq, Wk, Wv};

#define PISSUE(kc) { \
    if (wid == 0) { \
        unsigned mb = mb0 + ((kc) % 3) * 8; \
        if (l == 0) mbar_expect_tx(mb, PJ_XFERB); \
        __syncwarp(); \
        unsigned stg = smb + ((kc) % 3) * PJ_STAGEB; \
        _Pragma("unroll") for (int t = 0; t < 8; t++) { \
            int o = t * 32 + l;                 /* 0..255 */ \
            int sl = o >> 6, row = o & 63; \
            cp_bulk(stg + (sl * PJ_SLABF + row * PJ_PITCH) * 4, \
                    slabs[sl] + (size_t)row * EE + (kc) * 64, 256u, mb); \
        } \
    } }

    float acc[3][2][4][4];
#pragma unroll
    for (int mat = 0; mat < 3; mat++)
#pragma unroll
        for (int mi = 0; mi < 2; mi++)
#pragma unroll
            for (int nf = 0; nf < 4; nf++)
#pragma unroll
                for (int i = 0; i < 4; i++) acc[mat][mi][nf][i] = 0.0f;

    // fragment offsets within a stage (floats), k added separately (bytes)
    const unsigned aoffA[2] = {
        (unsigned)((m0 +      (l & 15)) * PJ_PITCH + ((l & 16) >> 2)),
        (unsigned)((m0 + 16 + (l & 15)) * PJ_PITCH + ((l & 16) >> 2)) };
    const unsigned boffB[2] = {
        (unsigned)((n0 +      (l & 7) + ((l & 16) >> 1)) * PJ_PITCH + ((l & 8) >> 1)),
        (unsigned)((n0 + 16 + (l & 7) + ((l & 16) >> 1)) * PJ_PITCH + ((l & 8) >> 1)) };

    PISSUE(0); PISSUE(1); PISSUE(2);

    for (int j = 0; j < 16; j++) {
        mbar_wait(mb0 + (j % 3) * 8, (unsigned)((j / 3) & 1));

        const unsigned stg = smb + (j % 3) * PJ_STAGEB;
#pragma unroll
        for (int k8 = 0; k8 < 4; k8++) {
            const unsigned kk = (kg * 32 + k8 * 8) * 4;     // byte offset of k
            unsigned a[2][4];
#pragma unroll
            for (int mi = 0; mi < 2; mi++) {
                LDSM4(a[mi][0], a[mi][1], a[mi][2], a[mi][3],
                      stg + aoffA[mi] * 4 + kk);
                a[mi][0] = u2tf32(a[mi][0]); a[mi][1] = u2tf32(a[mi][1]);
                a[mi][2] = u2tf32(a[mi][2]); a[mi][3] = u2tf32(a[mi][3]);
            }
#pragma unroll
            for (int mat = 0; mat < 3; mat++) {
                const unsigned mb = stg + (1 + mat) * (PJ_SLABF * 4);
#pragma unroll
                for (int np = 0; np < 2; np++) {
                    unsigned b0, b1, b2, b3;
                    LDSM4(b0, b1, b2, b3, mb + boffB[np] * 4 + kk);
                    b0 = u2tf32(b0); b1 = u2tf32(b1);
                    b2 = u2tf32(b2); b3 = u2tf32(b3);
#pragma unroll
                    for (int mi = 0; mi < 2; mi++) {
                        mma_tf32(acc[mat][mi][np*2    ], a[mi][0], a[mi][1], a[mi][2], a[mi][3], b0, b1);
                        mma_tf32(acc[mat][mi][np*2 + 1], a[mi][0], a[mi][1], a[mi][2], a[mi][3], b2, b3);
                    }
                }
            }
        }
        __syncthreads();        // all reads of stage done before refill
        if (j + 3 < 16) PISSUE(j + 3);
    }
#undef PISSUE

    // ---- k-split reduction: warps 4-7 publish, warps 0-3 combine ----
    __syncthreads();
    if (kg == 1) {
        float* red = psm + (tid - 128) * 96;
#pragma unroll
        for (int mat = 0; mat < 3; mat++)
#pragma unroll
            for (int mi = 0; mi < 2; mi++)
#pragma unroll
                for (int nf = 0; nf < 4; nf++)
#pragma unroll
                    for (int i = 0; i < 4; i++)
                        red[((mat*2 + mi)*4 + nf)*4 + i] = acc[mat][mi][nf][i];
    }
    __syncthreads();
    if (kg == 0) {
        const float* red = psm + tid * 96;
        const float* bs[3]  = {bq, bk, bv};
        float* outs[3] = {g_q, g_k, g_v};
#pragma unroll
        for (int mat = 0; mat < 3; mat++) {
#pragma unroll
            for (int mi = 0; mi < 2; mi++) {
#pragma unroll
                for (int nf = 0; nf < 4; nf++) {
                    const float* rp = red + ((mat*2 + mi)*4 + nf)*4;
                    int col = n0 + nf * 8 + 2 * tg;
                    float b0 = bs[mat][col], b1 = bs[mat][col + 1];
                    int r_lo = row0 + m0 + mi*16 + g;
                    float2 v0, v1;
                    v0.x = __uint_as_float(f2tf32(acc[mat][mi][nf][0] + rp[0] + b0));
                    v0.y = __uint_as_float(f2tf32(acc[mat][mi][nf][1] + rp[1] + b1));
                    v1.x = __uint_as_float(f2tf32(acc[mat][mi][nf][2] + rp[2] + b0));
                    v1.y = __uint_as_float(f2tf32(acc[mat][mi][nf][3] + rp[3] + b1));
                    *(float2*)(outs[mat] + (size_t)r_lo       * HH + col) = v0;
                    *(float2*)(outs[mat] + (size_t)(r_lo + 8) * HH + col) = v1;
                }
            }
        }
    }
}

// ---------------------------------------------------------------------------
// Kernel 2: causal flash attention, tf32 mma + ldmatrix, split-KV, cp.async.
// (unchanged, known good)
// ---------------------------------------------------------------------------
#define PITCH 68
#define TILE_F (64*PITCH)
#define QS_OFF 0
#define KS_OFF TILE_F
#define VS_OFF (KS_OFF + 4*TILE_F)
#define PS_OFF (VS_OFF + 4*TILE_F)
#define SM_FLOATS (PS_OFF + 8*16*PITCH)
#define SCL 0.18033688011112042f

__device__ __forceinline__ void attn_prefetch(
    float* sm, const float* kbase, const float* vbase,
    int tid, int tbase, int nt, int j)
{
    const int buf = j & 1;
#pragma unroll
    for (int t = 0; t < 16; t++) {
        int cidf = tid + t * 256;
        int sel  = cidf >> 10;
        int cid  = cidf & 1023;
        int row  = cid >> 4, c16 = cid & 15;
        int jt   = 2 * j + (sel & 1);
        if (jt < nt) {
            const float* src = ((sel >> 1) ? vbase : kbase)
                               + ((size_t)((tbase + jt) * 64 + row)) * HH + c16 * 4;
            float* dst = sm + ((sel >> 1) ? VS_OFF : KS_OFF)
                         + ((sel & 1) * 2 + buf) * TILE_F + row * PITCH + c16 * 4;
            cp16(dst, src);
        }
    }
}

__global__ __launch_bounds__(256) void attn_kernel(float* __restrict__ out)
{
    extern __shared__ float sm[];

    const int b   = blockIdx.y;
    const int tid = threadIdx.x;
    const int wid = tid >> 5, l = tid & 31, g = l >> 2, tg = l & 3;
    const int mt  = wid & 3;
    const int s   = wid >> 2;

    int qi = 0, ch = 0;
    {
        int wl = blockIdx.x, acc = 0;
        for (int ii = 31; ii >= 0; ii--) {
            int nc = (ii + 8) >> 3;
            if (wl < acc + nc) { qi = ii; ch = wl - acc; break; }
            acc += nc;
        }
    }
    const int qt0    = qi * 64;
    const int ntiles = qi + 1;
    const int nch    = (qi + 8) >> 3;
    const int tbase  = ch * 8;
    int nt = ntiles - tbase; if (nt > 8) nt = 8;
    const int ns = (nt + 1) >> 1;

    const float* kbase = g_k + (size_t)b * TT * HH;
    const float* vbase = g_v + (size_t)b * TT * HH;

    {
        const float* qsrc = g_q + ((size_t)b * TT + qt0) * HH;
#pragma unroll
        for (int t = 0; t < 4; t++) {
            int cid = tid + t * 256;
            int row = cid >> 4, c16 = cid & 15;
            cp16(sm + QS_OFF + row * PITCH + c16 * 4, qsrc + row * HH + c16 * 4);
        }
        attn_prefetch(sm, kbase, vbase, tid, tbase, nt, 0);
        CP_COMMIT();
    }

    const unsigned smu = (unsigned)__cvta_generic_to_shared(sm);
    const unsigned a16off = ((l & 15) * PITCH + ((l & 16) >> 2)) * 4;
    const unsigned bkoff  = (((l & 7) + ((l & 16) >> 1)) * PITCH + ((l & 8) >> 1)) * 4;
    const unsigned qs_u32 = smu + (QS_OFF + mt * 16 * PITCH) * 4 + a16off;
    const unsigned ps_u32 = smu + (PS_OFF + wid * 16 * PITCH) * 4 + a16off;

    unsigned qreg[8][4];
    float o[8][4];
    float m_lo = -INFINITY, m_hi = -INFINITY, l_lo = 0.f, l_hi = 0.f;
#pragma unroll
    for (int n = 0; n < 8; n++)
#pragma unroll
        for (int i = 0; i < 4; i++) o[n][i] = 0.0f;

    float* Ps = sm + PS_OFF + wid * (16 * PITCH);

    for (int j = 0; j < ns; j++) {
        const int buf = j & 1;
        if (j + 1 < ns) {
            attn_prefetch(sm, kbase, vbase, tid, tbase, nt, j + 1);
            CP_COMMIT();
            CP_WAIT1();
        } else {
            CP_WAIT0();
        }
        __syncthreads();

        if (j == 0) {
#pragma unroll
            for (int k8 = 0; k8 < 8; k8++)
                LDSM4(qreg[k8][0], qreg[k8][1], qreg[k8][2], qreg[k8][3],
                      qs_u32 + k8 * 32);
        }

        const int jt = 2 * j + s;
        if (jt < nt) {
            const int k0 = (tbase + jt) * 64;
            const unsigned kb_u32 = smu + (KS_OFF + (s * 2 + buf) * TILE_F) * 4 + bkoff;
            const float* Vb = sm + VS_OFF + (s * 2 + buf) * TILE_F;

            float sc[8][4];
#pragma unroll
            for (int n = 0; n < 8; n++)
#pragma unroll
                for (int i = 0; i < 4; i++) sc[n][i] = 0.0f;
#pragma unroll
            for (int k8 = 0; k8 < 8; k8++) {
#pragma unroll
                for (int n0p = 0; n0p < 4; n0p++) {
                    unsigned b0, b1, b2, b3;
                    LDSM4(b0, b1, b2, b3,
                          kb_u32 + n0p * (16 * PITCH * 4) + k8 * 32);
                    mma_tf32(sc[n0p*2    ], qreg[k8][0], qreg[k8][1], qreg[k8][2], qreg[k8][3], b0, b1);
                    mma_tf32(sc[n0p*2 + 1], qreg[k8][0], qreg[k8][1], qreg[k8][2], qreg[k8][3], b2, b3);
                }
            }

            const int t_lo = qt0 + mt*16 + g;
            const int t_hi = t_lo + 8;
            float mx_lo = -INFINITY, mx_hi = -INFINITY;
            float u[8][4];
#pragma unroll
            for (int n0 = 0; n0 < 8; n0++) {
                int c0 = k0 + n0*8 + 2*tg, c1 = c0 + 1;
                u[n0][0] = (c0 <= t_lo) ? sc[n0][0] * SCL : -INFINITY;
                u[n0][1] = (c1 <= t_lo) ? sc[n0][1] * SCL : -INFINITY;
                u[n0][2] = (c0 <= t_hi) ? sc[n0][2] * SCL : -INFINITY;
                u[n0][3] = (c1 <= t_hi) ? sc[n0][3] * SCL : -INFINITY;
                mx_lo = fmaxf(mx_lo, fmaxf(u[n0][0], u[n0][1]));
                mx_hi = fmaxf(mx_hi, fmaxf(u[n0][2], u[n0][3]));
            }
            mx_lo = fmaxf(mx_lo, __shfl_xor_sync(0xffffffffu, mx_lo, 1));
            mx_lo = fmaxf(mx_lo, __shfl_xor_sync(0xffffffffu, mx_lo, 2));
            mx_hi = fmaxf(mx_hi, __shfl_xor_sync(0xffffffffu, mx_hi, 1));
            mx_hi = fmaxf(mx_hi, __shfl_xor_sync(0xffffffffu, mx_hi, 2));
            float mn_lo = fmaxf(m_lo, mx_lo);
            float mn_hi = fmaxf(m_hi, mx_hi);
            float f_lo = ex2(m_lo - mn_lo);
            float f_hi = ex2(m_hi - mn_hi);

            float sum_lo = 0.f, sum_hi = 0.f;
#pragma unroll
            for (int n0 = 0; n0 < 8; n0++) {
                float p0 = ex2(u[n0][0] - mn_lo);
                float p1 = ex2(u[n0][1] - mn_lo);
                float p2 = ex2(u[n0][2] - mn_hi);
                float p3 = ex2(u[n0][3] - mn_hi);
                sum_lo += p0 + p1;
                sum_hi += p2 + p3;
                float2 w0, w1;
                w0.x = __uint_as_float(f2tf32(p0)); w0.y = __uint_as_float(f2tf32(p1));
                w1.x = __uint_as_float(f2tf32(p2)); w1.y = __uint_as_float(f2tf32(p3));
                *(float2*)(Ps + (g    ) * PITCH + n0*8 + 2*tg) = w0;
                *(float2*)(Ps + (g + 8) * PITCH + n0*8 + 2*tg) = w1;
            }
            sum_lo += __shfl_xor_sync(0xffffffffu, sum_lo, 1);
            sum_lo += __shfl_xor_sync(0xffffffffu, sum_lo, 2);
            sum_hi += __shfl_xor_sync(0xffffffffu, sum_hi, 1);
            sum_hi += __shfl_xor_sync(0xffffffffu, sum_hi, 2);
            l_lo = l_lo * f_lo + sum_lo;
            l_hi = l_hi * f_hi + sum_hi;
            m_lo = mn_lo; m_hi = mn_hi;
#pragma unroll
            for (int n0 = 0; n0 < 8; n0++) {
                o[n0][0] *= f_lo; o[n0][1] *= f_lo;
                o[n0][2] *= f_hi; o[n0][3] *= f_hi;
            }
            __syncwarp();

#pragma unroll
            for (int k8 = 0; k8 < 8; k8++) {
                unsigned a0, a1, a2, a3;
                LDSM4(a0, a1, a2, a3, ps_u32 + k8 * 32);
#pragma unroll
                for (int n0 = 0; n0 < 8; n0++) {
                    unsigned b0 = __float_as_uint(Vb[(k8*8 + tg    ) * PITCH + n0*8 + g]);
                    unsigned b1 = __float_as_uint(Vb[(k8*8 + tg + 4) * PITCH + n0*8 + g]);
                    mma_tf32(o[n0], a0, a1, a2, a3, b0, b1);
                }
            }
        }
        __syncthreads();
    }

    float* Om = sm + PS_OFF + mt * (16 * PITCH);
    float* Ml = sm + PS_OFF + 4 * (16 * PITCH) + mt * 32;
    if (s == 1) {
#pragma unroll
        for (int n0 = 0; n0 < 8; n0++) {
            *(float2*)(Om + (g    ) * PITCH + n0*8 + 2*tg) = make_float2(o[n0][0], o[n0][1]);
            *(float2*)(Om + (g + 8) * PITCH + n0*8 + 2*tg) = make_float2(o[n0][2], o[n0][3]);
        }
        Ml[g] = m_lo; Ml[g + 8] = m_hi;
        Ml[16 + g] = l_lo; Ml[16 + 8 + g] = l_hi;
    }
    __syncthreads();
    if (s == 0) {
        float m2_lo = Ml[g], m2_hi = Ml[g + 8];
        float l2_lo = Ml[16 + g], l2_hi = Ml[16 + 8 + g];
        float mf_lo = fmaxf(m_lo, m2_lo), mf_hi = fmaxf(m_hi, m2_hi);
        float a_lo = ex2(m_lo - mf_lo), b_lo = ex2(m2_lo - mf_lo);
        float a_hi = ex2(m_hi - mf_hi), b_hi = ex2(m2_hi - mf_hi);
        float lm_lo = l_lo * a_lo + l2_lo * b_lo;
        float lm_hi = l_hi * a_hi + l2_hi * b_hi;
        const int r_lo = mt*16 + g, r_hi = r_lo + 8;

        if (nch == 1) {
            float inv_lo = 1.0f / lm_lo, inv_hi = 1.0f / lm_hi;
#pragma unroll
            for (int n0 = 0; n0 < 8; n0++) {
                float2 o2l = *(float2*)(Om + (g    ) * PITCH + n0*8 + 2*tg);
                float2 o2h = *(float2*)(Om + (g + 8) * PITCH + n0*8 + 2*tg);
                float2 r0, r1;
                r0.x = (o[n0][0] * a_lo + o2l.x * b_lo) * inv_lo;
                r0.y = (o[n0][1] * a_lo + o2l.y * b_lo) * inv_lo;
                r1.x = (o[n0][2] * a_hi + o2h.x * b_hi) * inv_hi;
                r1.y = (o[n0][3] * a_hi + o2h.y * b_hi) * inv_hi;
                *(float2*)(out + ((size_t)b * TT + qt0 + r_lo) * HH + n0*8 + 2*tg) = r0;
                *(float2*)(out + ((size_t)b * TT + qt0 + r_hi) * HH + n0*8 + 2*tg) = r1;
            }
        } else {
            const int pidx = (b * 32 + qi) * 4 + ch;
            float* pod = g_po + (size_t)pidx * 4096;
#pragma unroll
            for (int n0 = 0; n0 < 8; n0++) {
                float2 o2l = *(float2*)(Om + (g    ) * PITCH + n0*8 + 2*tg);
                float2 o2h = *(float2*)(Om + (g + 8) * PITCH + n0*8 + 2*tg);
                float2 r0, r1;
                r0.x = o[n0][0] * a_lo + o2l.x * b_lo;
                r0.y = o[n0][1] * a_lo + o2l.y * b_lo;
                r1.x = o[n0][2] * a_hi + o2h.x * b_hi;
                r1.y = o[n0][3] * a_hi + o2h.y * b_hi;
                *(float2*)(pod + r_lo * 64 + n0*8 + 2*tg) = r0;
                *(float2*)(pod + r_hi * 64 + n0*8 + 2*tg) = r1;
            }
            if (tg == 0) {
                g_ml[pidx*128 + r_lo*2] = mf_lo; g_ml[pidx*128 + r_lo*2 + 1] = lm_lo;
                g_ml[pidx*128 + r_hi*2] = mf_hi; g_ml[pidx*128 + r_hi*2 + 1] = lm_hi;
            }
        }
    }
}

// ---------------------------------------------------------------------------
// Kernel 3: merge split-KV partials (qi >= 8).  grid (24, 4), block 256.
// ---------------------------------------------------------------------------
__global__ __launch_bounds__(256) void merge_kernel(float* __restrict__ out)
{
    const int qi  = 8 + blockIdx.x;
    const int b   = blockIdx.y;
    const int nch = (qi + 8) >> 3;
    const int tid = threadIdx.x;
    const int r   = tid >> 2;
    const int cg  = (tid & 3) * 16;
    const int pbase = (b * 32 + qi) * 4;

    float mv[4], lv[4], e[4];
    float mf = -INFINITY;
    for (int c = 0; c < nch; c++) {
        mv[c] = g_ml[(pbase + c)*128 + r*2];
        lv[c] = g_ml[(pbase + c)*128 + r*2 + 1];
        mf = fmaxf(mf, mv[c]);
    }
    float wsum = 0.f;
    for (int c = 0; c < nch; c++) { e[c] = ex2(mv[c] - mf); wsum += lv[c] * e[c]; }
    float inv = 1.0f / wsum;

    size_t obase = ((size_t)b * TT + qi * 64 + r) * HH;
#pragma unroll
    for (int c4 = 0; c4 < 4; c4++) {
        float4 a = make_float4(0.f, 0.f, 0.f, 0.f);
        for (int c = 0; c < nch; c++) {
            const float4 p = *(const float4*)(g_po + (size_t)(pbase + c)*4096 + r*64 + cg + c4*4);
            a.x += e[c]*p.x; a.y += e[c]*p.y; a.z += e[c]*p.z; a.w += e[c]*p.w;
        }
        a.x *= inv; a.y *= inv; a.z *= inv; a.w *= inv;
        *(float4*)(out + obase + cg + c4*4) = a;
    }
}

// ---------------------------------------------------------------------------
extern "C" void kernel_launch(void* const* d_in, const int* in_sizes, int n_in,
                              void* d_out, int out_size)
{
    const float* x  = (const float*)d_in[0];
    const float* Wq = (const float*)d_in[1];
    const float* bq = (const float*)d_in[2];
    const float* Wk = (const float*)d_in[3];
    const float* bk = (const float*)d_in[4];
    const float* Wv = (const float*)d_in[5];
    const float* bv = (const float*)d_in[6];
    float* out = (float*)d_out;

    cudaFuncSetAttribute(proj_kernel, cudaFuncAttributeMaxDynamicSharedMemorySize, PJ_SM_BYTES);
    proj_kernel<<<MM / 64, 256, PJ_SM_BYTES>>>(x, Wq, bq, Wk, bk, Wv, bv);

    const int smem_bytes = SM_FLOATS * sizeof(float);
    cudaFuncSetAttribute(attn_kernel, cudaFuncAttributeMaxDynamicSharedMemorySize, smem_bytes);
    attn_kernel<<<dim3(80, BB), 256, smem_bytes>>>(out);

    merge_kernel<<<dim3(24, BB), 256>>>(out);
}

// round 13
// speedup vs baseline: 2.2900x; 2.2900x over previous
#include <cuda_runtime.h>
#include <math.h>

#define BB 4
#define TT 2048
#define EE 1024
#define HH 64
#define MM (BB*TT)

// device scratch (module statics: allocation-free)
__device__ float g_q[MM*HH];
__device__ float g_k[MM*HH];
__device__ float g_v[MM*HH];
// split-KV partials: pidx = (b*32 + qtile)*8 + chunk   (chunk of 4 KV tiles)
__device__ float g_po[1024*64*64];
__device__ float g_ml[1024*64*2];

__device__ __forceinline__ unsigned f2tf32(float f) {
    unsigned u;
    asm("cvt.rna.tf32.f32 %0, %1;" : "=r"(u) : "f"(f));
    return u;
}
__device__ __forceinline__ unsigned u2tf32(unsigned ub) {
    unsigned u;
    asm("cvt.rna.tf32.f32 %0, %1;" : "=r"(u) : "f"(__uint_as_float(ub)));
    return u;
}
__device__ __forceinline__ float ex2(float x) {
    float y;
    asm("ex2.approx.ftz.f32 %0, %1;" : "=f"(y) : "f"(x));
    return y;
}
__device__ __forceinline__ void mma_tf32(float c[4], unsigned a0, unsigned a1,
                                         unsigned a2, unsigned a3,
                                         unsigned b0, unsigned b1) {
    asm volatile(
        "mma.sync.aligned.m16n8k8.row.col.f32.tf32.tf32.f32 "
        "{%0,%1,%2,%3}, {%4,%5,%6,%7}, {%8,%9}, {%0,%1,%2,%3};"
        : "+f"(c[0]), "+f"(c[1]), "+f"(c[2]), "+f"(c[3])
        : "r"(a0), "r"(a1), "r"(a2), "r"(a3), "r"(b0), "r"(b1));
}
#define LDSM4(r0,r1,r2,r3,addr) \
    asm volatile("ldmatrix.sync.aligned.m8n8.x4.shared.b16 {%0,%1,%2,%3}, [%4];" \
                 : "=r"(r0), "=r"(r1), "=r"(r2), "=r"(r3) : "r"(addr))

__device__ __forceinline__ void cp16(void* smem, const void* gmem) {
    unsigned sa = (unsigned)__cvta_generic_to_shared(smem);
    asm volatile("cp.async.cg.shared.global [%0], [%1], 16;" :: "r"(sa), "l"(gmem));
}
#define CP_COMMIT() asm volatile("cp.async.commit_group;")
#define CP_WAIT0()  asm volatile("cp.async.wait_group 0;")
#define CP_WAIT1()  asm volatile("cp.async.wait_group 1;")

// ---------------------------------------------------------------------------
// Kernel 1: FUSED QKV projection (R10 configuration — fastest measured).
// grid 128 (64 rows/block), block 256 (8 warps).
// Warp tiling 2m x 2n x 2k; 32 K-chunks of 32; 3-stage cp.async(cg) ring.
// Pitch 36 floats.  kg=1 partials reduced into kg=0 via smem.
// ---------------------------------------------------------------------------
#define PJ_PITCH 36
#define PJ_MATF  (64*PJ_PITCH)            // 2304 floats per matrix slab
#define PJ_STAGE (4*PJ_MATF)              // 9216 floats per stage
#define PJ_SM_FLOATS (3*PJ_STAGE)         // 27648 -> 110592 bytes

__global__ __launch_bounds__(256) void proj_kernel(
    const float* __restrict__ x,
    const float* __restrict__ Wq, const float* __restrict__ bq,
    const float* __restrict__ Wk, const float* __restrict__ bk,
    const float* __restrict__ Wv, const float* __restrict__ bv)
{
    extern __shared__ __align__(16) float psm[];

    const int row0 = blockIdx.x * 64;
    const int tid  = threadIdx.x;
    const int wid  = tid >> 5, l = tid & 31;
    const int g    = l >> 2, tg = l & 3;
    const int m0   = (wid & 1) * 32;
    const int n0   = ((wid >> 1) & 1) * 32;
    const int kg   = wid >> 2;

    const float* srcp[4];
    srcp[0] = x + (size_t)row0 * EE;
    srcp[1] = Wq; srcp[2] = Wk; srcp[3] = Wv;

#define PPREF(kc) { \
    float* stage = psm + ((kc) % 3) * PJ_STAGE; \
    _Pragma("unroll") for (int mmat = 0; mmat < 4; mmat++) { \
        _Pragma("unroll") for (int t = 0; t < 2; t++) { \
            int idx = tid + t * 256; \
            int row = idx >> 3, u = idx & 7; \
            cp16(stage + mmat * PJ_MATF + row * PJ_PITCH + u * 4, \
                 srcp[mmat] + (size_t)row * EE + (kc) * 32 + u * 4); \
        } \
    } \
    CP_COMMIT(); }

    float acc[3][2][4][4];
#pragma unroll
    for (int mat = 0; mat < 3; mat++)
#pragma unroll
        for (int mi = 0; mi < 2; mi++)
#pragma unroll
            for (int nf = 0; nf < 4; nf++)
#pragma unroll
                for (int i = 0; i < 4; i++) acc[mat][mi][nf][i] = 0.0f;

    const unsigned sb = (unsigned)__cvta_generic_to_shared(psm);
    const unsigned aoffA[2] = {
        (unsigned)((m0 +      (l & 15)) * PJ_PITCH + ((l & 16) >> 2)),
        (unsigned)((m0 + 16 + (l & 15)) * PJ_PITCH + ((l & 16) >> 2)) };
    const unsigned boffB[2] = {
        (unsigned)((n0 +      (l & 7) + ((l & 16) >> 1)) * PJ_PITCH + ((l & 8) >> 1)),
        (unsigned)((n0 + 16 + (l & 7) + ((l & 16) >> 1)) * PJ_PITCH + ((l & 8) >> 1)) };

    PPREF(0); PPREF(1);

    for (int j = 0; j < 32; j++) {
        if (j < 31) { CP_WAIT1(); } else { CP_WAIT0(); }
        __syncthreads();

        const unsigned stg = sb + (j % 3) * (PJ_STAGE * 4);
#pragma unroll
        for (int k8 = 0; k8 < 2; k8++) {
            const unsigned kk = (kg * 16 + k8 * 8) * 4;
            unsigned a[2][4];
#pragma unroll
            for (int mi = 0; mi < 2; mi++) {
                LDSM4(a[mi][0], a[mi][1], a[mi][2], a[mi][3],
                      stg + aoffA[mi] * 4 + kk);
                a[mi][0] = u2tf32(a[mi][0]); a[mi][1] = u2tf32(a[mi][1]);
                a[mi][2] = u2tf32(a[mi][2]); a[mi][3] = u2tf32(a[mi][3]);
            }
#pragma unroll
            for (int mat = 0; mat < 3; mat++) {
                const unsigned mb = stg + (1 + mat) * (PJ_MATF * 4);
#pragma unroll
                for (int np = 0; np < 2; np++) {
                    unsigned b0, b1, b2, b3;
                    LDSM4(b0, b1, b2, b3, mb + boffB[np] * 4 + kk);
                    b0 = u2tf32(b0); b1 = u2tf32(b1);
                    b2 = u2tf32(b2); b3 = u2tf32(b3);
#pragma unroll
                    for (int mi = 0; mi < 2; mi++) {
                        mma_tf32(acc[mat][mi][np*2    ], a[mi][0], a[mi][1], a[mi][2], a[mi][3], b0, b1);
                        mma_tf32(acc[mat][mi][np*2 + 1], a[mi][0], a[mi][1], a[mi][2], a[mi][3], b2, b3);
                    }
                }
            }
        }
        if (j + 2 < 32) PPREF(j + 2);
    }
#undef PPREF

    // ---- k-split reduction: warps 4-7 publish, warps 0-3 combine ----
    __syncthreads();
    if (kg == 1) {
        float* red = psm + (tid - 128) * 96;
#pragma unroll
        for (int mat = 0; mat < 3; mat++)
#pragma unroll
            for (int mi = 0; mi < 2; mi++)
#pragma unroll
                for (int nf = 0; nf < 4; nf++)
#pragma unroll
                    for (int i = 0; i < 4; i++)
                        red[((mat*2 + mi)*4 + nf)*4 + i] = acc[mat][mi][nf][i];
    }
    __syncthreads();
    if (kg == 0) {
        const float* red = psm + tid * 96;
        const float* bs[3]  = {bq, bk, bv};
        float* outs[3] = {g_q, g_k, g_v};
#pragma unroll
        for (int mat = 0; mat < 3; mat++) {
#pragma unroll
            for (int mi = 0; mi < 2; mi++) {
#pragma unroll
                for (int nf = 0; nf < 4; nf++) {
                    const float* rp = red + ((mat*2 + mi)*4 + nf)*4;
                    int col = n0 + nf * 8 + 2 * tg;
                    float b0 = bs[mat][col], b1 = bs[mat][col + 1];
                    int r_lo = row0 + m0 + mi*16 + g;
                    float2 v0, v1;
                    v0.x = __uint_as_float(f2tf32(acc[mat][mi][nf][0] + rp[0] + b0));
                    v0.y = __uint_as_float(f2tf32(acc[mat][mi][nf][1] + rp[1] + b1));
                    v1.x = __uint_as_float(f2tf32(acc[mat][mi][nf][2] + rp[2] + b0));
                    v1.y = __uint_as_float(f2tf32(acc[mat][mi][nf][3] + rp[3] + b1));
                    *(float2*)(outs[mat] + (size_t)r_lo       * HH + col) = v0;
                    *(float2*)(outs[mat] + (size_t)(r_lo + 8) * HH + col) = v1;
                }
            }
        }
    }
}

// ---------------------------------------------------------------------------
// Kernel 2: causal flash attention, tf32 mma + ldmatrix, split-KV, cp.async.
// CHANGE vs R10: finer split-KV — chunk = 4 KV tiles (was 8).
// grid = (144, 4): 144 = sum over qi of ceil((qi+1)/4), heavy qi first.
// ns <= 2 supersteps per block -> per-SM work quantum nearly uniform.
// ---------------------------------------------------------------------------
#define PITCH 68
#define TILE_F (64*PITCH)
#define QS_OFF 0
#define KS_OFF TILE_F
#define VS_OFF (KS_OFF + 4*TILE_F)
#define PS_OFF (VS_OFF + 4*TILE_F)
#define SM_FLOATS (PS_OFF + 8*16*PITCH)
#define SCL 0.18033688011112042f

__device__ __forceinline__ void attn_prefetch(
    float* sm, const float* kbase, const float* vbase,
    int tid, int tbase, int nt, int j)
{
    const int buf = j & 1;
#pragma unroll
    for (int t = 0; t < 16; t++) {
        int cidf = tid + t * 256;
        int sel  = cidf >> 10;
        int cid  = cidf & 1023;
        int row  = cid >> 4, c16 = cid & 15;
        int jt   = 2 * j + (sel & 1);
        if (jt < nt) {
            const float* src = ((sel >> 1) ? vbase : kbase)
                               + ((size_t)((tbase + jt) * 64 + row)) * HH + c16 * 4;
            float* dst = sm + ((sel >> 1) ? VS_OFF : KS_OFF)
                         + ((sel & 1) * 2 + buf) * TILE_F + row * PITCH + c16 * 4;
            cp16(dst, src);
        }
    }
}

__global__ __launch_bounds__(256) void attn_kernel(float* __restrict__ out)
{
    extern __shared__ float sm[];

    const int b   = blockIdx.y;
    const int tid = threadIdx.x;
    const int wid = tid >> 5, l = tid & 31, g = l >> 2, tg = l & 3;
    const int mt  = wid & 3;
    const int s   = wid >> 2;

    // worklist decode: heavy q-tiles first; chunk = 4 KV tiles
    int qi = 0, ch = 0;
    {
        int wl = blockIdx.x, acc = 0;
        for (int ii = 31; ii >= 0; ii--) {
            int nc = (ii + 4) >> 2;            // ceil((ii+1)/4)
            if (wl < acc + nc) { qi = ii; ch = wl - acc; break; }
            acc += nc;
        }
    }
    const int qt0    = qi * 64;
    const int ntiles = qi + 1;
    const int nch    = (qi + 4) >> 2;
    const int tbase  = ch * 4;
    int nt = ntiles - tbase; if (nt > 4) nt = 4;
    const int ns = (nt + 1) >> 1;

    const float* kbase = g_k + (size_t)b * TT * HH;
    const float* vbase = g_v + (size_t)b * TT * HH;

    {
        const float* qsrc = g_q + ((size_t)b * TT + qt0) * HH;
#pragma unroll
        for (int t = 0; t < 4; t++) {
            int cid = tid + t * 256;
            int row = cid >> 4, c16 = cid & 15;
            cp16(sm + QS_OFF + row * PITCH + c16 * 4, qsrc + row * HH + c16 * 4);
        }
        attn_prefetch(sm, kbase, vbase, tid, tbase, nt, 0);
        CP_COMMIT();
    }

    const unsigned smu = (unsigned)__cvta_generic_to_shared(sm);
    const unsigned a16off = ((l & 15) * PITCH + ((l & 16) >> 2)) * 4;
    const unsigned bkoff  = (((l & 7) + ((l & 16) >> 1)) * PITCH + ((l & 8) >> 1)) * 4;
    const unsigned qs_u32 = smu + (QS_OFF + mt * 16 * PITCH) * 4 + a16off;
    const unsigned ps_u32 = smu + (PS_OFF + wid * 16 * PITCH) * 4 + a16off;

    unsigned qreg[8][4];
    float o[8][4];
    float m_lo = -INFINITY, m_hi = -INFINITY, l_lo = 0.f, l_hi = 0.f;
#pragma unroll
    for (int n = 0; n < 8; n++)
#pragma unroll
        for (int i = 0; i < 4; i++) o[n][i] = 0.0f;

    float* Ps = sm + PS_OFF + wid * (16 * PITCH);

    for (int j = 0; j < ns; j++) {
        const int buf = j & 1;
        if (j + 1 < ns) {
            attn_prefetch(sm, kbase, vbase, tid, tbase, nt, j + 1);
            CP_COMMIT();
            CP_WAIT1();
        } else {
            CP_WAIT0();
        }
        __syncthreads();

        if (j == 0) {
#pragma unroll
            for (int k8 = 0; k8 < 8; k8++)
                LDSM4(qreg[k8][0], qreg[k8][1], qreg[k8][2], qreg[k8][3],
                      qs_u32 + k8 * 32);
        }

        const int jt = 2 * j + s;
        if (jt < nt) {
            const int k0 = (tbase + jt) * 64;
            const unsigned kb_u32 = smu + (KS_OFF + (s * 2 + buf) * TILE_F) * 4 + bkoff;
            const float* Vb = sm + VS_OFF + (s * 2 + buf) * TILE_F;

            float sc[8][4];
#pragma unroll
            for (int n = 0; n < 8; n++)
#pragma unroll
                for (int i = 0; i < 4; i++) sc[n][i] = 0.0f;
#pragma unroll
            for (int k8 = 0; k8 < 8; k8++) {
#pragma unroll
                for (int n0p = 0; n0p < 4; n0p++) {
                    unsigned b0, b1, b2, b3;
                    LDSM4(b0, b1, b2, b3,
                          kb_u32 + n0p * (16 * PITCH * 4) + k8 * 32);
                    mma_tf32(sc[n0p*2    ], qreg[k8][0], qreg[k8][1], qreg[k8][2], qreg[k8][3], b0, b1);
                    mma_tf32(sc[n0p*2 + 1], qreg[k8][0], qreg[k8][1], qreg[k8][2], qreg[k8][3], b2, b3);
                }
            }

            const int t_lo = qt0 + mt*16 + g;
            const int t_hi = t_lo + 8;
            float mx_lo = -INFINITY, mx_hi = -INFINITY;
            float u[8][4];
#pragma unroll
            for (int n0 = 0; n0 < 8; n0++) {
                int c0 = k0 + n0*8 + 2*tg, c1 = c0 + 1;
                u[n0][0] = (c0 <= t_lo) ? sc[n0][0] * SCL : -INFINITY;
                u[n0][1] = (c1 <= t_lo) ? sc[n0][1] * SCL : -INFINITY;
                u[n0][2] = (c0 <= t_hi) ? sc[n0][2] * SCL : -INFINITY;
                u[n0][3] = (c1 <= t_hi) ? sc[n0][3] * SCL : -INFINITY;
                mx_lo = fmaxf(mx_lo, fmaxf(u[n0][0], u[n0][1]));
                mx_hi = fmaxf(mx_hi, fmaxf(u[n0][2], u[n0][3]));
            }
            mx_lo = fmaxf(mx_lo, __shfl_xor_sync(0xffffffffu, mx_lo, 1));
            mx_lo = fmaxf(mx_lo, __shfl_xor_sync(0xffffffffu, mx_lo, 2));
            mx_hi = fmaxf(mx_hi, __shfl_xor_sync(0xffffffffu, mx_hi, 1));
            mx_hi = fmaxf(mx_hi, __shfl_xor_sync(0xffffffffu, mx_hi, 2));
            float mn_lo = fmaxf(m_lo, mx_lo);
            float mn_hi = fmaxf(m_hi, mx_hi);
            float f_lo = ex2(m_lo - mn_lo);
            float f_hi = ex2(m_hi - mn_hi);

            float sum_lo = 0.f, sum_hi = 0.f;
#pragma unroll
            for (int n0 = 0; n0 < 8; n0++) {
                float p0 = ex2(u[n0][0] - mn_lo);
                float p1 = ex2(u[n0][1] - mn_lo);
                float p2 = ex2(u[n0][2] - mn_hi);
                float p3 = ex2(u[n0][3] - mn_hi);
                sum_lo += p0 + p1;
                sum_hi += p2 + p3;
                float2 w0, w1;
                w0.x = __uint_as_float(f2tf32(p0)); w0.y = __uint_as_float(f2tf32(p1));
                w1.x = __uint_as_float(f2tf32(p2)); w1.y = __uint_as_float(f2tf32(p3));
                *(float2*)(Ps + (g    ) * PITCH + n0*8 + 2*tg) = w0;
                *(float2*)(Ps + (g + 8) * PITCH + n0*8 + 2*tg) = w1;
            }
            sum_lo += __shfl_xor_sync(0xffffffffu, sum_lo, 1);
            sum_lo += __shfl_xor_sync(0xffffffffu, sum_lo, 2);
            sum_hi += __shfl_xor_sync(0xffffffffu, sum_hi, 1);
            sum_hi += __shfl_xor_sync(0xffffffffu, sum_hi, 2);
            l_lo = l_lo * f_lo + sum_lo;
            l_hi = l_hi * f_hi + sum_hi;
            m_lo = mn_lo; m_hi = mn_hi;
#pragma unroll
            for (int n0 = 0; n0 < 8; n0++) {
                o[n0][0] *= f_lo; o[n0][1] *= f_lo;
                o[n0][2] *= f_hi; o[n0][3] *= f_hi;
            }
            __syncwarp();

#pragma unroll
            for (int k8 = 0; k8 < 8; k8++) {
                unsigned a0, a1, a2, a3;
                LDSM4(a0, a1, a2, a3, ps_u32 + k8 * 32);
#pragma unroll
                for (int n0 = 0; n0 < 8; n0++) {
                    unsigned b0 = __float_as_uint(Vb[(k8*8 + tg    ) * PITCH + n0*8 + g]);
                    unsigned b1 = __float_as_uint(Vb[(k8*8 + tg + 4) * PITCH + n0*8 + g]);
                    mma_tf32(o[n0], a0, a1, a2, a3, b0, b1);
                }
            }
        }
        __syncthreads();
    }

    // ---- merge the two streams; write out or partials ----
    float* Om = sm + PS_OFF + mt * (16 * PITCH);
    float* Ml = sm + PS_OFF + 4 * (16 * PITCH) + mt * 32;
    if (s == 1) {
#pragma unroll
        for (int n0 = 0; n0 < 8; n0++) {
            *(float2*)(Om + (g    ) * PITCH + n0*8 + 2*tg) = make_float2(o[n0][0], o[n0][1]);
            *(float2*)(Om + (g + 8) * PITCH + n0*8 + 2*tg) = make_float2(o[n0][2], o[n0][3]);
        }
        Ml[g] = m_lo; Ml[g + 8] = m_hi;
        Ml[16 + g] = l_lo; Ml[16 + 8 + g] = l_hi;
    }
    __syncthreads();
    if (s == 0) {
        float m2_lo = Ml[g], m2_hi = Ml[g + 8];
        float l2_lo = Ml[16 + g], l2_hi = Ml[16 + 8 + g];
        float mf_lo = fmaxf(m_lo, m2_lo), mf_hi = fmaxf(m_hi, m2_hi);
        float a_lo = ex2(m_lo - mf_lo), b_lo = ex2(m2_lo - mf_lo);
        float a_hi = ex2(m_hi - mf_hi), b_hi = ex2(m2_hi - mf_hi);
        float lm_lo = l_lo * a_lo + l2_lo * b_lo;
        float lm_hi = l_hi * a_hi + l2_hi * b_hi;
        const int r_lo = mt*16 + g, r_hi = r_lo + 8;

        if (nch == 1) {
            float inv_lo = 1.0f / lm_lo, inv_hi = 1.0f / lm_hi;
#pragma unroll
            for (int n0 = 0; n0 < 8; n0++) {
                float2 o2l = *(float2*)(Om + (g    ) * PITCH + n0*8 + 2*tg);
                float2 o2h = *(float2*)(Om + (g + 8) * PITCH + n0*8 + 2*tg);
                float2 r0, r1;
                r0.x = (o[n0][0] * a_lo + o2l.x * b_lo) * inv_lo;
                r0.y = (o[n0][1] * a_lo + o2l.y * b_lo) * inv_lo;
                r1.x = (o[n0][2] * a_hi + o2h.x * b_hi) * inv_hi;
                r1.y = (o[n0][3] * a_hi + o2h.y * b_hi) * inv_hi;
                *(float2*)(out + ((size_t)b * TT + qt0 + r_lo) * HH + n0*8 + 2*tg) = r0;
                *(float2*)(out + ((size_t)b * TT + qt0 + r_hi) * HH + n0*8 + 2*tg) = r1;
            }
        } else {
            const int pidx = (b * 32 + qi) * 8 + ch;
            float* pod = g_po + (size_t)pidx * 4096;
#pragma unroll
            for (int n0 = 0; n0 < 8; n0++) {
                float2 o2l = *(float2*)(Om + (g    ) * PITCH + n0*8 + 2*tg);
                float2 o2h = *(float2*)(Om + (g + 8) * PITCH + n0*8 + 2*tg);
                float2 r0, r1;
                r0.x = o[n0][0] * a_lo + o2l.x * b_lo;
                r0.y = o[n0][1] * a_lo + o2l.y * b_lo;
                r1.x = o[n0][2] * a_hi + o2h.x * b_hi;
                r1.y = o[n0][3] * a_hi + o2h.y * b_hi;
                *(float2*)(pod + r_lo * 64 + n0*8 + 2*tg) = r0;
                *(float2*)(pod + r_hi * 64 + n0*8 + 2*tg) = r1;
            }
            if (tg == 0) {
                g_ml[pidx*128 + r_lo*2] = mf_lo; g_ml[pidx*128 + r_lo*2 + 1] = lm_lo;
                g_ml[pidx*128 + r_hi*2] = mf_hi; g_ml[pidx*128 + r_hi*2 + 1] = lm_hi;
            }
        }
    }
}

// ---------------------------------------------------------------------------
// Kernel 3: merge split-KV partials (qi >= 4; up to 8 chunks).
// grid (28, 4), block 256: thread -> (row = tid/4, 16 cols).
// ---------------------------------------------------------------------------
__global__ __launch_bounds__(256) void merge_kernel(float* __restrict__ out)
{
    const int qi  = 4 + blockIdx.x;
    const int b   = blockIdx.y;
    const int nch = (qi + 4) >> 2;        // 2..8
    const int tid = threadIdx.x;
    const int r   = tid >> 2;
    const int cg  = (tid & 3) * 16;
    const int pbase = (b * 32 + qi) * 8;

    float mv[8], lv[8], e[8];
    float mf = -INFINITY;
    for (int c = 0; c < nch; c++) {
        mv[c] = g_ml[(pbase + c)*128 + r*2];
        lv[c] = g_ml[(pbase + c)*128 + r*2 + 1];
        mf = fmaxf(mf, mv[c]);
    }
    float wsum = 0.f;
    for (int c = 0; c < nch; c++) { e[c] = ex2(mv[c] - mf); wsum += lv[c] * e[c]; }
    float inv = 1.0f / wsum;

    size_t obase = ((size_t)b * TT + qi * 64 + r) * HH;
#pragma unroll
    for (int c4 = 0; c4 < 4; c4++) {
        float4 a = make_float4(0.f, 0.f, 0.f, 0.f);
        for (int c = 0; c < nch; c++) {
            const float4 p = *(const float4*)(g_po + (size_t)(pbase + c)*4096 + r*64 + cg + c4*4);
            a.x += e[c]*p.x; a.y += e[c]*p.y; a.z += e[c]*p.z; a.w += e[c]*p.w;
        }
        a.x *= inv; a.y *= inv; a.z *= inv; a.w *= inv;
        *(float4*)(out + obase + cg + c4*4) = a;
    }
}

// ---------------------------------------------------------------------------
extern "C" void kernel_launch(void* const* d_in, const int* in_sizes, int n_in,
                              void* d_out, int out_size)
{
    const float* x  = (const float*)d_in[0];
    const float* Wq = (const float*)d_in[1];
    const float* bq = (const float*)d_in[2];
    const float* Wk = (const float*)d_in[3];
    const float* bk = (const float*)d_in[4];
    const float* Wv = (const float*)d_in[5];
    const float* bv = (const float*)d_in[6];
    float* out = (float*)d_out;

    const int proj_smem = PJ_SM_FLOATS * sizeof(float);   // 110592
    cudaFuncSetAttribute(proj_kernel, cudaFuncAttributeMaxDynamicSharedMemorySize, proj_smem);
    proj_kernel<<<MM / 64, 256, proj_smem>>>(x, Wq, bq, Wk, bk, Wv, bv);

    const int smem_bytes = SM_FLOATS * sizeof(float);
    cudaFuncSetAttribute(attn_kernel, cudaFuncAttributeMaxDynamicSharedMemorySize, smem_bytes);
    attn_kernel<<<dim3(144, BB), 256, smem_bytes>>>(out);

    merge_kernel<<<dim3(28, BB), 256>>>(out);
}

// round 14
// speedup vs baseline: 2.4760x; 1.0812x over previous
#include <cuda_runtime.h>
#include <math.h>

#define BB 4
#define TT 2048
#define EE 1024
#define HH 64
#define MM (BB*TT)

// device scratch (module statics: allocation-free)
__device__ float g_q[MM*HH];
__device__ float g_k[MM*HH];
__device__ float g_v[MM*HH];
// split-KV partials: pidx = (b*32 + qtile)*4 + chunk   (chunk of 8 KV tiles)
__device__ float g_po[512*64*64];
__device__ float g_ml[512*64*2];

__device__ __forceinline__ unsigned f2tf32(float f) {
    unsigned u;
    asm("cvt.rna.tf32.f32 %0, %1;" : "=r"(u) : "f"(f));
    return u;
}
__device__ __forceinline__ unsigned u2tf32(unsigned ub) {
    unsigned u;
    asm("cvt.rna.tf32.f32 %0, %1;" : "=r"(u) : "f"(__uint_as_float(ub)));
    return u;
}
__device__ __forceinline__ float ex2(float x) {
    float y;
    asm("ex2.approx.ftz.f32 %0, %1;" : "=f"(y) : "f"(x));
    return y;
}
__device__ __forceinline__ void mma_tf32(float c[4], unsigned a0, unsigned a1,
                                         unsigned a2, unsigned a3,
                                         unsigned b0, unsigned b1) {
    asm volatile(
        "mma.sync.aligned.m16n8k8.row.col.f32.tf32.tf32.f32 "
        "{%0,%1,%2,%3}, {%4,%5,%6,%7}, {%8,%9}, {%0,%1,%2,%3};"
        : "+f"(c[0]), "+f"(c[1]), "+f"(c[2]), "+f"(c[3])
        : "r"(a0), "r"(a1), "r"(a2), "r"(a3), "r"(b0), "r"(b1));
}
#define LDSM4(r0,r1,r2,r3,addr) \
    asm volatile("ldmatrix.sync.aligned.m8n8.x4.shared.b16 {%0,%1,%2,%3}, [%4];" \
                 : "=r"(r0), "=r"(r1), "=r"(r2), "=r"(r3) : "r"(addr))

__device__ __forceinline__ void cp16(void* smem, const void* gmem) {
    unsigned sa = (unsigned)__cvta_generic_to_shared(smem);
    asm volatile("cp.async.cg.shared.global [%0], [%1], 16;" :: "r"(sa), "l"(gmem));
}
#define CP_COMMIT() asm volatile("cp.async.commit_group;")
#define CP_WAIT0()  asm volatile("cp.async.wait_group 0;")
#define CP_WAIT1()  asm volatile("cp.async.wait_group 1;")

// ---------------------------------------------------------------------------
// Kernel 1: FUSED QKV projection (R10 configuration — fastest measured).
// grid 128 (64 rows/block), block 256 (8 warps).
// Warp tiling 2m x 2n x 2k; 32 K-chunks of 32; 3-stage cp.async(cg) ring.
// Pitch 36 floats.  kg=1 partials reduced into kg=0 via smem.
// ---------------------------------------------------------------------------
#define PJ_PITCH 36
#define PJ_MATF  (64*PJ_PITCH)
#define PJ_STAGE (4*PJ_MATF)
#define PJ_SM_FLOATS (3*PJ_STAGE)

__global__ __launch_bounds__(256) void proj_kernel(
    const float* __restrict__ x,
    const float* __restrict__ Wq, const float* __restrict__ bq,
    const float* __restrict__ Wk, const float* __restrict__ bk,
    const float* __restrict__ Wv, const float* __restrict__ bv)
{
    extern __shared__ __align__(16) float psm[];

    const int row0 = blockIdx.x * 64;
    const int tid  = threadIdx.x;
    const int wid  = tid >> 5, l = tid & 31;
    const int g    = l >> 2, tg = l & 3;
    const int m0   = (wid & 1) * 32;
    const int n0   = ((wid >> 1) & 1) * 32;
    const int kg   = wid >> 2;

    const float* srcp[4];
    srcp[0] = x + (size_t)row0 * EE;
    srcp[1] = Wq; srcp[2] = Wk; srcp[3] = Wv;

#define PPREF(kc) { \
    float* stage = psm + ((kc) % 3) * PJ_STAGE; \
    _Pragma("unroll") for (int mmat = 0; mmat < 4; mmat++) { \
        _Pragma("unroll") for (int t = 0; t < 2; t++) { \
            int idx = tid + t * 256; \
            int row = idx >> 3, u = idx & 7; \
            cp16(stage + mmat * PJ_MATF + row * PJ_PITCH + u * 4, \
                 srcp[mmat] + (size_t)row * EE + (kc) * 32 + u * 4); \
        } \
    } \
    CP_COMMIT(); }

    float acc[3][2][4][4];
#pragma unroll
    for (int mat = 0; mat < 3; mat++)
#pragma unroll
        for (int mi = 0; mi < 2; mi++)
#pragma unroll
            for (int nf = 0; nf < 4; nf++)
#pragma unroll
                for (int i = 0; i < 4; i++) acc[mat][mi][nf][i] = 0.0f;

    const unsigned sb = (unsigned)__cvta_generic_to_shared(psm);
    const unsigned aoffA[2] = {
        (unsigned)((m0 +      (l & 15)) * PJ_PITCH + ((l & 16) >> 2)),
        (unsigned)((m0 + 16 + (l & 15)) * PJ_PITCH + ((l & 16) >> 2)) };
    const unsigned boffB[2] = {
        (unsigned)((n0 +      (l & 7) + ((l & 16) >> 1)) * PJ_PITCH + ((l & 8) >> 1)),
        (unsigned)((n0 + 16 + (l & 7) + ((l & 16) >> 1)) * PJ_PITCH + ((l & 8) >> 1)) };

    PPREF(0); PPREF(1);

    for (int j = 0; j < 32; j++) {
        if (j < 31) { CP_WAIT1(); } else { CP_WAIT0(); }
        __syncthreads();

        const unsigned stg = sb + (j % 3) * (PJ_STAGE * 4);
#pragma unroll
        for (int k8 = 0; k8 < 2; k8++) {
            const unsigned kk = (kg * 16 + k8 * 8) * 4;
            unsigned a[2][4];
#pragma unroll
            for (int mi = 0; mi < 2; mi++) {
                LDSM4(a[mi][0], a[mi][1], a[mi][2], a[mi][3],
                      stg + aoffA[mi] * 4 + kk);
                a[mi][0] = u2tf32(a[mi][0]); a[mi][1] = u2tf32(a[mi][1]);
                a[mi][2] = u2tf32(a[mi][2]); a[mi][3] = u2tf32(a[mi][3]);
            }
#pragma unroll
            for (int mat = 0; mat < 3; mat++) {
                const unsigned mb = stg + (1 + mat) * (PJ_MATF * 4);
#pragma unroll
                for (int np = 0; np < 2; np++) {
                    unsigned b0, b1, b2, b3;
                    LDSM4(b0, b1, b2, b3, mb + boffB[np] * 4 + kk);
                    b0 = u2tf32(b0); b1 = u2tf32(b1);
                    b2 = u2tf32(b2); b3 = u2tf32(b3);
#pragma unroll
                    for (int mi = 0; mi < 2; mi++) {
                        mma_tf32(acc[mat][mi][np*2    ], a[mi][0], a[mi][1], a[mi][2], a[mi][3], b0, b1);
                        mma_tf32(acc[mat][mi][np*2 + 1], a[mi][0], a[mi][1], a[mi][2], a[mi][3], b2, b3);
                    }
                }
            }
        }
        if (j + 2 < 32) PPREF(j + 2);
    }
#undef PPREF

    __syncthreads();
    if (kg == 1) {
        float* red = psm + (tid - 128) * 96;
#pragma unroll
        for (int mat = 0; mat < 3; mat++)
#pragma unroll
            for (int mi = 0; mi < 2; mi++)
#pragma unroll
                for (int nf = 0; nf < 4; nf++)
#pragma unroll
                    for (int i = 0; i < 4; i++)
                        red[((mat*2 + mi)*4 + nf)*4 + i] = acc[mat][mi][nf][i];
    }
    __syncthreads();
    if (kg == 0) {
        const float* red = psm + tid * 96;
        const float* bs[3]  = {bq, bk, bv};
        float* outs[3] = {g_q, g_k, g_v};
#pragma unroll
        for (int mat = 0; mat < 3; mat++) {
#pragma unroll
            for (int mi = 0; mi < 2; mi++) {
#pragma unroll
                for (int nf = 0; nf < 4; nf++) {
                    const float* rp = red + ((mat*2 + mi)*4 + nf)*4;
                    int col = n0 + nf * 8 + 2 * tg;
                    float b0 = bs[mat][col], b1 = bs[mat][col + 1];
                    int r_lo = row0 + m0 + mi*16 + g;
                    float2 v0, v1;
                    v0.x = __uint_as_float(f2tf32(acc[mat][mi][nf][0] + rp[0] + b0));
                    v0.y = __uint_as_float(f2tf32(acc[mat][mi][nf][1] + rp[1] + b1));
                    v1.x = __uint_as_float(f2tf32(acc[mat][mi][nf][2] + rp[2] + b0));
                    v1.y = __uint_as_float(f2tf32(acc[mat][mi][nf][3] + rp[3] + b1));
                    *(float2*)(outs[mat] + (size_t)r_lo       * HH + col) = v0;
                    *(float2*)(outs[mat] + (size_t)(r_lo + 8) * HH + col) = v1;
                }
            }
        }
    }
}

// ---------------------------------------------------------------------------
// Kernel 2: causal flash attention, tf32 mma + ldmatrix, split-KV.
// CHANGE vs R10: smem cut 191KB -> 102KB for 2 blocks/SM:
//   - K/V single-buffered per stream (no intra-block double buffering;
//     inter-block overlap via occupancy replaces it)
//   - Q staging overlaid on the P-scratch region (Q consumed into regs at
//     j==0 before any P write; extra sync makes it race-free)
// grid (80, 4), chunk = 8 KV tiles (R10 chunking, best measured).
// ---------------------------------------------------------------------------
#define PITCH 68
#define TILE_F (64*PITCH)
#define KS_OFF 0
#define VS_OFF (2*TILE_F)
#define PS_OFF (4*TILE_F)                  // also Q staging area (64 rows x PITCH)
#define SM_FLOATS (PS_OFF + 8*16*PITCH)    // 26112 floats = 104448 B
#define SCL 0.18033688011112042f

__device__ __forceinline__ void attn_prefetch(
    float* sm, const float* kbase, const float* vbase,
    int tid, int tbase, int nt, int j)
{
#pragma unroll
    for (int t = 0; t < 16; t++) {
        int cidf = tid + t * 256;
        int sel  = cidf >> 10;             // 0:K s0  1:K s1  2:V s0  3:V s1
        int cid  = cidf & 1023;
        int row  = cid >> 4, c16 = cid & 15;
        int jt   = 2 * j + (sel & 1);
        if (jt < nt) {
            const float* src = ((sel >> 1) ? vbase : kbase)
                               + ((size_t)((tbase + jt) * 64 + row)) * HH + c16 * 4;
            float* dst = sm + ((sel >> 1) ? VS_OFF : KS_OFF)
                         + (sel & 1) * TILE_F + row * PITCH + c16 * 4;
            cp16(dst, src);
        }
    }
}

__global__ __launch_bounds__(256, 2) void attn_kernel(float* __restrict__ out)
{
    extern __shared__ float sm[];

    const int b   = blockIdx.y;
    const int tid = threadIdx.x;
    const int wid = tid >> 5, l = tid & 31, g = l >> 2, tg = l & 3;
    const int mt  = wid & 3;
    const int s   = wid >> 2;

    int qi = 0, ch = 0;
    {
        int wl = blockIdx.x, acc = 0;
        for (int ii = 31; ii >= 0; ii--) {
            int nc = (ii + 8) >> 3;
            if (wl < acc + nc) { qi = ii; ch = wl - acc; break; }
            acc += nc;
        }
    }
    const int qt0    = qi * 64;
    const int ntiles = qi + 1;
    const int nch    = (qi + 8) >> 3;
    const int tbase  = ch * 8;
    int nt = ntiles - tbase; if (nt > 8) nt = 8;
    const int ns = (nt + 1) >> 1;

    const float* kbase = g_k + (size_t)b * TT * HH;
    const float* vbase = g_v + (size_t)b * TT * HH;

    // prologue: Q tile into PS region + superstep 0 K/V
    {
        const float* qsrc = g_q + ((size_t)b * TT + qt0) * HH;
#pragma unroll
        for (int t = 0; t < 4; t++) {
            int cid = tid + t * 256;
            int row = cid >> 4, c16 = cid & 15;
            cp16(sm + PS_OFF + row * PITCH + c16 * 4, qsrc + row * HH + c16 * 4);
        }
        attn_prefetch(sm, kbase, vbase, tid, tbase, nt, 0);
        CP_COMMIT();
    }

    const unsigned smu = (unsigned)__cvta_generic_to_shared(sm);
    const unsigned a16off = ((l & 15) * PITCH + ((l & 16) >> 2)) * 4;
    const unsigned bkoff  = (((l & 7) + ((l & 16) >> 1)) * PITCH + ((l & 8) >> 1)) * 4;
    const unsigned ps_u32 = smu + (PS_OFF + wid * 16 * PITCH) * 4 + a16off;
    const unsigned qs_u32 = smu + (PS_OFF + mt * 16 * PITCH) * 4 + a16off;

    unsigned qreg[8][4];
    float o[8][4];
    float m_lo = -INFINITY, m_hi = -INFINITY, l_lo = 0.f, l_hi = 0.f;
#pragma unroll
    for (int n = 0; n < 8; n++)
#pragma unroll
        for (int i = 0; i < 4; i++) o[n][i] = 0.0f;

    float* Ps = sm + PS_OFF + wid * (16 * PITCH);

    for (int j = 0; j < ns; j++) {
        CP_WAIT0();
        __syncthreads();

        if (j == 0) {       // Q fragments -> registers, then release PS region
#pragma unroll
            for (int k8 = 0; k8 < 8; k8++)
                LDSM4(qreg[k8][0], qreg[k8][1], qreg[k8][2], qreg[k8][3],
                      qs_u32 + k8 * 32);
            __syncthreads();   // qreg loads done before any warp writes P here
        }

        const int jt = 2 * j + s;
        if (jt < nt) {
            const int k0 = (tbase + jt) * 64;
            const unsigned kb_u32 = smu + (KS_OFF + s * TILE_F) * 4 + bkoff;
            const float* Vb = sm + VS_OFF + s * TILE_F;

            // ---- S = Q . K^T ----
            float sc[8][4];
#pragma unroll
            for (int n = 0; n < 8; n++)
#pragma unroll
                for (int i = 0; i < 4; i++) sc[n][i] = 0.0f;
#pragma unroll
            for (int k8 = 0; k8 < 8; k8++) {
#pragma unroll
                for (int n0p = 0; n0p < 4; n0p++) {
                    unsigned b0, b1, b2, b3;
                    LDSM4(b0, b1, b2, b3,
                          kb_u32 + n0p * (16 * PITCH * 4) + k8 * 32);
                    mma_tf32(sc[n0p*2    ], qreg[k8][0], qreg[k8][1], qreg[k8][2], qreg[k8][3], b0, b1);
                    mma_tf32(sc[n0p*2 + 1], qreg[k8][0], qreg[k8][1], qreg[k8][2], qreg[k8][3], b2, b3);
                }
            }

            // ---- masked online softmax (mask in place; log2 domain) ----
            const int t_lo = qt0 + mt*16 + g;
            const int t_hi = t_lo + 8;
            float mx_lo = -INFINITY, mx_hi = -INFINITY;
#pragma unroll
            for (int n0 = 0; n0 < 8; n0++) {
                int c0 = k0 + n0*8 + 2*tg, c1 = c0 + 1;
                sc[n0][0] = (c0 <= t_lo) ? sc[n0][0] * SCL : -INFINITY;
                sc[n0][1] = (c1 <= t_lo) ? sc[n0][1] * SCL : -INFINITY;
                sc[n0][2] = (c0 <= t_hi) ? sc[n0][2] * SCL : -INFINITY;
                sc[n0][3] = (c1 <= t_hi) ? sc[n0][3] * SCL : -INFINITY;
                mx_lo = fmaxf(mx_lo, fmaxf(sc[n0][0], sc[n0][1]));
                mx_hi = fmaxf(mx_hi, fmaxf(sc[n0][2], sc[n0][3]));
            }
            mx_lo = fmaxf(mx_lo, __shfl_xor_sync(0xffffffffu, mx_lo, 1));
            mx_lo = fmaxf(mx_lo, __shfl_xor_sync(0xffffffffu, mx_lo, 2));
            mx_hi = fmaxf(mx_hi, __shfl_xor_sync(0xffffffffu, mx_hi, 1));
            mx_hi = fmaxf(mx_hi, __shfl_xor_sync(0xffffffffu, mx_hi, 2));
            float mn_lo = fmaxf(m_lo, mx_lo);
            float mn_hi = fmaxf(m_hi, mx_hi);
            float f_lo = ex2(m_lo - mn_lo);
            float f_hi = ex2(m_hi - mn_hi);

            float sum_lo = 0.f, sum_hi = 0.f;
#pragma unroll
            for (int n0 = 0; n0 < 8; n0++) {
                float p0 = ex2(sc[n0][0] - mn_lo);
                float p1 = ex2(sc[n0][1] - mn_lo);
                float p2 = ex2(sc[n0][2] - mn_hi);
                float p3 = ex2(sc[n0][3] - mn_hi);
                sum_lo += p0 + p1;
                sum_hi += p2 + p3;
                float2 w0, w1;
                w0.x = __uint_as_float(f2tf32(p0)); w0.y = __uint_as_float(f2tf32(p1));
                w1.x = __uint_as_float(f2tf32(p2)); w1.y = __uint_as_float(f2tf32(p3));
                *(float2*)(Ps + (g    ) * PITCH + n0*8 + 2*tg) = w0;
                *(float2*)(Ps + (g + 8) * PITCH + n0*8 + 2*tg) = w1;
            }
            sum_lo += __shfl_xor_sync(0xffffffffu, sum_lo, 1);
            sum_lo += __shfl_xor_sync(0xffffffffu, sum_lo, 2);
            sum_hi += __shfl_xor_sync(0xffffffffu, sum_hi, 1);
            sum_hi += __shfl_xor_sync(0xffffffffu, sum_hi, 2);
            l_lo = l_lo * f_lo + sum_lo;
            l_hi = l_hi * f_hi + sum_hi;
            m_lo = mn_lo; m_hi = mn_hi;
#pragma unroll
            for (int n0 = 0; n0 < 8; n0++) {
                o[n0][0] *= f_lo; o[n0][1] *= f_lo;
                o[n0][2] *= f_hi; o[n0][3] *= f_hi;
            }
            __syncwarp();

            // ---- O += P . V ----
#pragma unroll
            for (int k8 = 0; k8 < 8; k8++) {
                unsigned a0, a1, a2, a3;
                LDSM4(a0, a1, a2, a3, ps_u32 + k8 * 32);
#pragma unroll
                for (int n0 = 0; n0 < 8; n0++) {
                    unsigned b0 = __float_as_uint(Vb[(k8*8 + tg    ) * PITCH + n0*8 + g]);
                    unsigned b1 = __float_as_uint(Vb[(k8*8 + tg + 4) * PITCH + n0*8 + g]);
                    mma_tf32(o[n0], a0, a1, a2, a3, b0, b1);
                }
            }
        }
        __syncthreads();        // K/V reads done before refill
        if (j + 1 < ns) {
            attn_prefetch(sm, kbase, vbase, tid, tbase, nt, j + 1);
            CP_COMMIT();
        }
    }

    // ---- merge the two streams; write out or partials ----
    __syncthreads();
    float* Om = sm + PS_OFF + mt * (16 * PITCH);
    float* Ml = sm + PS_OFF + 4 * (16 * PITCH) + mt * 32;
    if (s == 1) {
#pragma unroll
        for (int n0 = 0; n0 < 8; n0++) {
            *(float2*)(Om + (g    ) * PITCH + n0*8 + 2*tg) = make_float2(o[n0][0], o[n0][1]);
            *(float2*)(Om + (g + 8) * PITCH + n0*8 + 2*tg) = make_float2(o[n0][2], o[n0][3]);
        }
        Ml[g] = m_lo; Ml[g + 8] = m_hi;
        Ml[16 + g] = l_lo; Ml[16 + 8 + g] = l_hi;
    }
    __syncthreads();
    if (s == 0) {
        float m2_lo = Ml[g], m2_hi = Ml[g + 8];
        float l2_lo = Ml[16 + g], l2_hi = Ml[16 + 8 + g];
        float mf_lo = fmaxf(m_lo, m2_lo), mf_hi = fmaxf(m_hi, m2_hi);
        float a_lo = ex2(m_lo - mf_lo), b_lo = ex2(m2_lo - mf_lo);
        float a_hi = ex2(m_hi - mf_hi), b_hi = ex2(m2_hi - mf_hi);
        float lm_lo = l_lo * a_lo + l2_lo * b_lo;
        float lm_hi = l_hi * a_hi + l2_hi * b_hi;
        const int r_lo = mt*16 + g, r_hi = r_lo + 8;

        if (nch == 1) {
            float inv_lo = 1.0f / lm_lo, inv_hi = 1.0f / lm_hi;
#pragma unroll
            for (int n0 = 0; n0 < 8; n0++) {
                float2 o2l = *(float2*)(Om + (g    ) * PITCH + n0*8 + 2*tg);
                float2 o2h = *(float2*)(Om + (g + 8) * PITCH + n0*8 + 2*tg);
                float2 r0, r1;
                r0.x = (o[n0][0] * a_lo + o2l.x * b_lo) * inv_lo;
                r0.y = (o[n0][1] * a_lo + o2l.y * b_lo) * inv_lo;
                r1.x = (o[n0][2] * a_hi + o2h.x * b_hi) * inv_hi;
                r1.y = (o[n0][3] * a_hi + o2h.y * b_hi) * inv_hi;
                *(float2*)(out + ((size_t)b * TT + qt0 + r_lo) * HH + n0*8 + 2*tg) = r0;
                *(float2*)(out + ((size_t)b * TT + qt0 + r_hi) * HH + n0*8 + 2*tg) = r1;
            }
        } else {
            const int pidx = (b * 32 + qi) * 4 + ch;
            float* pod = g_po + (size_t)pidx * 4096;
#pragma unroll
            for (int n0 = 0; n0 < 8; n0++) {
                float2 o2l = *(float2*)(Om + (g    ) * PITCH + n0*8 + 2*tg);
                float2 o2h = *(float2*)(Om + (g + 8) * PITCH + n0*8 + 2*tg);
                float2 r0, r1;
                r0.x = o[n0][0] * a_lo + o2l.x * b_lo;
                r0.y = o[n0][1] * a_lo + o2l.y * b_lo;
                r1.x = o[n0][2] * a_hi + o2h.x * b_hi;
                r1.y = o[n0][3] * a_hi + o2h.y * b_hi;
                *(float2*)(pod + r_lo * 64 + n0*8 + 2*tg) = r0;
                *(float2*)(pod + r_hi * 64 + n0*8 + 2*tg) = r1;
            }
            if (tg == 0) {
                g_ml[pidx*128 + r_lo*2] = mf_lo; g_ml[pidx*128 + r_lo*2 + 1] = lm_lo;
                g_ml[pidx*128 + r_hi*2] = mf_hi; g_ml[pidx*128 + r_hi*2 + 1] = lm_hi;
            }
        }
    }
}

// ---------------------------------------------------------------------------
// Kernel 3: merge split-KV partials (qi >= 8).  grid (24, 4), block 256.
// ---------------------------------------------------------------------------
__global__ __launch_bounds__(256) void merge_kernel(float* __restrict__ out)
{
    const int qi  = 8 + blockIdx.x;
    const int b   = blockIdx.y;
    const int nch = (qi + 8) >> 3;
    const int tid = threadIdx.x;
    const int r   = tid >> 2;
    const int cg  = (tid & 3) * 16;
    const int pbase = (b * 32 + qi) * 4;

    float mv[4], lv[4], e[4];
    float mf = -INFINITY;
    for (int c = 0; c < nch; c++) {
        mv[c] = g_ml[(pbase + c)*128 + r*2];
        lv[c] = g_ml[(pbase + c)*128 + r*2 + 1];
        mf = fmaxf(mf, mv[c]);
    }
    float wsum = 0.f;
    for (int c = 0; c < nch; c++) { e[c] = ex2(mv[c] - mf); wsum += lv[c] * e[c]; }
    float inv = 1.0f / wsum;

    size_t obase = ((size_t)b * TT + qi * 64 + r) * HH;
#pragma unroll
    for (int c4 = 0; c4 < 4; c4++) {
        float4 a = make_float4(0.f, 0.f, 0.f, 0.f);
        for (int c = 0; c < nch; c++) {
            const float4 p = *(const float4*)(g_po + (size_t)(pbase + c)*4096 + r*64 + cg + c4*4);
            a.x += e[c]*p.x; a.y += e[c]*p.y; a.z += e[c]*p.z; a.w += e[c]*p.w;
        }
        a.x *= inv; a.y *= inv; a.z *= inv; a.w *= inv;
        *(float4*)(out + obase + cg + c4*4) = a;
    }
}

// ---------------------------------------------------------------------------
extern "C" void kernel_launch(void* const* d_in, const int* in_sizes, int n_in,
                              void* d_out, int out_size)
{
    const float* x  = (const float*)d_in[0];
    const float* Wq = (const float*)d_in[1];
    const float* bq = (const float*)d_in[2];
    const float* Wk = (const float*)d_in[3];
    const float* bk = (const float*)d_in[4];
    const float* Wv = (const float*)d_in[5];
    const float* bv = (const float*)d_in[6];
    float* out = (float*)d_out;

    const int proj_smem = PJ_SM_FLOATS * sizeof(float);   // 110592
    cudaFuncSetAttribute(proj_kernel, cudaFuncAttributeMaxDynamicSharedMemorySize, proj_smem);
    proj_kernel<<<MM / 64, 256, proj_smem>>>(x, Wq, bq, Wk, bk, Wv, bv);

    const int smem_bytes = SM_FLOATS * sizeof(float);     // 104448
    cudaFuncSetAttribute(attn_kernel, cudaFuncAttributeMaxDynamicSharedMemorySize, smem_bytes);
    attn_kernel<<<dim3(80, BB), 256, smem_bytes>>>(out);

    merge_kernel<<<dim3(24, BB), 256>>>(out);
}